// round 10
// baseline (speedup 1.0000x reference)
#include <cuda_runtime.h>
#include <mma.h>
#include <math.h>
#include <stdint.h>

using namespace nvcuda;

#define N_TOK 4096
#define D_DIM 2048
#define F_DIM 8192
#define E_EXP 8
#define R_RANK 8
#define SCALING 2.0f

#define BM 128
#define BN 128
#define BK 16
#define TM 8
#define TN 8

// ---------------- scratch ----------------------------------------------------
__device__ float x_hi[(size_t)N_TOK * D_DIM];
__device__ float x_lo[(size_t)N_TOK * D_DIM];
__device__ float w1h[(size_t)F_DIM * D_DIM];
__device__ float w1l[(size_t)F_DIM * D_DIM];
__device__ float w2h[(size_t)D_DIM * F_DIM];
__device__ float w2l[(size_t)D_DIM * F_DIM];
__device__ float g_hi[(size_t)N_TOK * F_DIM];
__device__ float g_lo[(size_t)N_TOK * F_DIM];
__device__ float C1[(size_t)N_TOK * F_DIM];
__device__ float C2[(size_t)N_TOK * D_DIM];
__device__ float h_buf[2ull * N_TOK * F_DIM];
__device__ float z1c[N_TOK * 16];
__device__ float z2s[N_TOK * 16];
__device__ int   eidx[N_TOK * 2];
__device__ float ew[N_TOK * 2];
__device__ float wsum_buf[N_TOK];
__device__ int gf1, gf2;

__device__ __forceinline__ float gelu_new(float x) {
    float x3 = x * x * x;
    float t = tanhf(0.7978845608028654f * (x + 0.044715f * x3));
    return 0.5f * x * (1.0f + t);
}

__global__ void reset_kernel(){ gf1 = 0; gf2 = 0; }

// ---------------- tf32 split conversion --------------------------------------
__global__ __launch_bounds__(256) void cvt_split(
    const float* __restrict__ src, float* __restrict__ hi, float* __restrict__ lo,
    int cols)
{
    int row = blockIdx.x;
    const float4* s = (const float4*)(src + (size_t)row * cols);
    float4* dh = (float4*)(hi + (size_t)row * cols);
    float4* dl = (float4*)(lo + (size_t)row * cols);
    for (int i = threadIdx.x; i < cols / 4; i += 256){
        float4 v = s[i];
        float4 h, l;
        h.x = wmma::__float_to_tf32(v.x); l.x = wmma::__float_to_tf32(v.x - h.x);
        h.y = wmma::__float_to_tf32(v.y); l.y = wmma::__float_to_tf32(v.y - h.y);
        h.z = wmma::__float_to_tf32(v.z); l.z = wmma::__float_to_tf32(v.z - h.z);
        h.w = wmma::__float_to_tf32(v.w); l.w = wmma::__float_to_tf32(v.w - h.w);
        dh[i] = h; dl[i] = l;
    }
}

// ---------------- router — verbatim R1 ---------------------------------------
__global__ __launch_bounds__(256) void router_kernel(
    const float* __restrict__ x, const float* __restrict__ Wr,
    const float* __restrict__ br, const float* __restrict__ A1)
{
    int n = blockIdx.x;
    int tid = threadIdx.x;
    __shared__ float xs[D_DIM];
    __shared__ float red[16][8];
    __shared__ int s_idx[2];

    for (int d = tid; d < D_DIM; d += 256) xs[d] = x[(size_t)n * D_DIM + d];
    __syncthreads();

    float acc[E_EXP];
#pragma unroll
    for (int e = 0; e < E_EXP; e++) acc[e] = 0.f;
    for (int d = tid; d < D_DIM; d += 256) {
        float xv = xs[d];
#pragma unroll
        for (int e = 0; e < E_EXP; e++) acc[e] += xv * Wr[e * D_DIM + d];
    }
#pragma unroll
    for (int e = 0; e < E_EXP; e++) {
        float v = acc[e];
        for (int o = 16; o > 0; o >>= 1) v += __shfl_down_sync(0xffffffffu, v, o);
        if ((tid & 31) == 0) red[e][tid >> 5] = v;
    }
    __syncthreads();

    if (tid == 0) {
        float lg[E_EXP];
#pragma unroll
        for (int e = 0; e < E_EXP; e++) {
            float v = 0.f;
#pragma unroll
            for (int w = 0; w < 8; w++) v += red[e][w];
            lg[e] = v + br[e];
        }
        float mx = lg[0];
#pragma unroll
        for (int e = 1; e < E_EXP; e++) mx = fmaxf(mx, lg[e]);
        float p[E_EXP], se = 0.f;
#pragma unroll
        for (int e = 0; e < E_EXP; e++) { p[e] = expf(lg[e] - mx); se += p[e]; }
        float inv = 1.0f / se;
#pragma unroll
        for (int e = 0; e < E_EXP; e++) p[e] *= inv;
        int i0 = 0;
#pragma unroll
        for (int e = 1; e < E_EXP; e++) if (p[e] > p[i0]) i0 = e;
        int i1 = -1;
#pragma unroll
        for (int e = 0; e < E_EXP; e++) {
            if (e == i0) continue;
            if (i1 < 0 || p[e] > p[i1]) i1 = e;
        }
        s_idx[0] = i0; s_idx[1] = i1;
        eidx[2 * n] = i0; eidx[2 * n + 1] = i1;
        ew[2 * n] = p[i0]; ew[2 * n + 1] = p[i1];
        wsum_buf[n] = p[i0] + p[i1];
    }
    __syncthreads();

    int e0 = s_idx[0], e1 = s_idx[1];
    float u[16];
#pragma unroll
    for (int i = 0; i < 16; i++) u[i] = 0.f;
    for (int d = tid; d < D_DIM; d += 256) {
        float xv = xs[d];
#pragma unroll
        for (int r = 0; r < R_RANK; r++) {
            u[r]     += xv * A1[((size_t)e0 * R_RANK + r) * D_DIM + d];
            u[8 + r] += xv * A1[((size_t)e1 * R_RANK + r) * D_DIM + d];
        }
    }
    __syncthreads();
#pragma unroll
    for (int i = 0; i < 16; i++) {
        float v = u[i];
        for (int o = 16; o > 0; o >>= 1) v += __shfl_down_sync(0xffffffffu, v, o);
        if ((tid & 31) == 0) red[i][tid >> 5] = v;
    }
    __syncthreads();
    if (tid < 16) {
        float v = 0.f;
#pragma unroll
        for (int w = 0; w < 8; w++) v += red[tid][w];
        z1c[n * 16 + tid] = v * SCALING;
    }
}

// ============================================================================
// tf32 single-pass GEMM: C[128,128] (+)= A[128,K] . B[128,K]^T
// Operands are PRE-SPLIT (tf32-valued fp32) -> no conversions in mainloop.
// ============================================================================
typedef wmma::fragment<wmma::matrix_a, 16,16,8, wmma::precision::tf32, wmma::row_major> TFA;
typedef wmma::fragment<wmma::matrix_b, 16,16,8, wmma::precision::tf32, wmma::col_major> TFB;
typedef wmma::fragment<wmma::accumulator, 16,16,8, float> TFC;

__device__ __forceinline__ void ldg_tile(float4* r, const float* g, size_t stride, int tid){
#pragma unroll
    for (int i = 0; i < 2; i++){
        int idx = tid + i * 256;
        int row = idx >> 2, c = (idx & 3) * 4;
        r[i] = *(const float4*)(g + (size_t)row * stride + c);
    }
}
__device__ __forceinline__ void sts_tile(float* s, const float4* r, int tid){
#pragma unroll
    for (int i = 0; i < 2; i++){
        int idx = tid + i * 256;
        int row = idx >> 2, c = (idx & 3) * 4;
        *(float4*)(s + row * 20 + c) = r[i];
    }
}

__global__ __launch_bounds__(256) void gemm_pass(
    const float* __restrict__ Ag, const float* __restrict__ Bg,
    float* __restrict__ C, int K, int ldc, int init)
{
    __shared__ __align__(16) float smem[10240];   // 2 stages x (A 2560 + B 2560)
    int bn = blockIdx.x, bm = blockIdx.y;
    int tid = threadIdx.x, wid = tid >> 5;
    int wr = wid & 3, wc = wid >> 2;               // 4 M-warps x 2 N-warps
    const float* Ab = Ag + (size_t)bm * 128 * K;
    const float* Bb = Bg + (size_t)bn * 128 * K;
    float* Cb = C + (size_t)bm * 128 * ldc + bn * 128;

    TFC acc[2][4];
    if (init){
#pragma unroll
        for (int i = 0; i < 2; i++)
#pragma unroll
        for (int j = 0; j < 4; j++) wmma::fill_fragment(acc[i][j], 0.f);
    } else {
#pragma unroll
        for (int i = 0; i < 2; i++)
#pragma unroll
        for (int j = 0; j < 4; j++)
            wmma::load_matrix_sync(acc[i][j],
                Cb + (size_t)(wr*32 + i*16) * ldc + wc*64 + j*16, ldc,
                wmma::mem_row_major);
    }

    int nch = K / BK;
    float4 ra[2], rb[2];
    ldg_tile(ra, Ab, K, tid);
    ldg_tile(rb, Bb, K, tid);
    sts_tile(smem,        ra, tid);
    sts_tile(smem + 2560, rb, tid);
    __syncthreads();

    for (int c = 0; c < nch; c++){
        if (c + 1 < nch){
            ldg_tile(ra, Ab + (size_t)(c+1)*BK, K, tid);
            ldg_tile(rb, Bb + (size_t)(c+1)*BK, K, tid);
        }
        const float* sA = smem + (c & 1) * 5120;
        const float* sB = sA + 2560;
#pragma unroll
        for (int k8 = 0; k8 < 2; k8++){
            TFA a[2];
            TFB b[4];
#pragma unroll
            for (int i = 0; i < 2; i++)
                wmma::load_matrix_sync(a[i], sA + (wr*32 + i*16)*20 + k8*8, 20);
#pragma unroll
            for (int j = 0; j < 4; j++)
                wmma::load_matrix_sync(b[j], sB + (wc*64 + j*16)*20 + k8*8, 20);
#pragma unroll
            for (int i = 0; i < 2; i++)
#pragma unroll
            for (int j = 0; j < 4; j++)
                wmma::mma_sync(acc[i][j], a[i], b[j], acc[i][j]);
        }
        if (c + 1 < nch){
            float* d = smem + ((c+1) & 1) * 5120;
            sts_tile(d,        ra, tid);
            sts_tile(d + 2560, rb, tid);
        }
        __syncthreads();
    }

#pragma unroll
    for (int i = 0; i < 2; i++)
#pragma unroll
    for (int j = 0; j < 4; j++)
        wmma::store_matrix_sync(Cb + (size_t)(wr*32 + i*16) * ldc + wc*64 + j*16,
                                acc[i][j], ldc, wmma::mem_row_major);
}

// ============================================================================
// Epilogues
// ============================================================================
__global__ __launch_bounds__(256) void fc1_epi(
    const float* __restrict__ b1, const float* __restrict__ B1)
{
    int n = blockIdx.x, tid = threadIdx.x;
    int e0 = eidx[2*n], e1 = eidx[2*n+1];
    float w0 = ew[2*n], w1w = ew[2*n+1];
    float z0[8], z1[8];
#pragma unroll
    for (int r = 0; r < 8; r++){ z0[r] = z1c[n*16+r]; z1[r] = z1c[n*16+8+r]; }
    const float* crow = C1 + (size_t)n * F_DIM;
    float* ph0 = h_buf + (size_t)n * F_DIM;
    float* ph1 = ph0 + (size_t)N_TOK * F_DIM;
    float* pgh = g_hi + (size_t)n * F_DIM;
    float* pgl = g_lo + (size_t)n * F_DIM;

    for (int f4 = tid * 4; f4 < F_DIM; f4 += 1024){
        float4 cv = *(const float4*)(crow + f4);
        float4 bv = *(const float4*)(b1 + f4);
        float c[4] = {cv.x + bv.x, cv.y + bv.y, cv.z + bv.z, cv.w + bv.w};
        float4 h0o, h1o, gh, gl;
        float* h0p = (float*)&h0o; float* h1p = (float*)&h1o;
        float* ghp = (float*)&gh;  float* glp = (float*)&gl;
#pragma unroll
        for (int q = 0; q < 4; q++){
            int f = f4 + q;
            const float4* q0 = (const float4*)&B1[((size_t)e0*F_DIM + f)*R_RANK];
            const float4* q1 = (const float4*)&B1[((size_t)e1*F_DIM + f)*R_RANK];
            float4 u0 = q0[0], u1 = q0[1], v0 = q1[0], v1 = q1[1];
            float l0 = z0[0]*u0.x + z0[1]*u0.y + z0[2]*u0.z + z0[3]*u0.w
                     + z0[4]*u1.x + z0[5]*u1.y + z0[6]*u1.z + z0[7]*u1.w;
            float l1 = z1[0]*v0.x + z1[1]*v0.y + z1[2]*v0.z + z1[3]*v0.w
                     + z1[4]*v1.x + z1[5]*v1.y + z1[6]*v1.z + z1[7]*v1.w;
            float h0 = gelu_new(c[q] + l0);
            float h1 = gelu_new(c[q] + l1);
            float g  = w0*h0 + w1w*h1;
            h0p[q] = h0; h1p[q] = h1;
            float gh_ = wmma::__float_to_tf32(g);
            ghp[q] = gh_;
            glp[q] = wmma::__float_to_tf32(g - gh_);
        }
        *(float4*)(ph0 + f4) = h0o;
        *(float4*)(ph1 + f4) = h1o;
        *(float4*)(pgh + f4) = gh;
        *(float4*)(pgl + f4) = gl;
    }
}

__global__ __launch_bounds__(256) void fc2_epi(
    const float* __restrict__ b2, const float* __restrict__ B2,
    float* __restrict__ out)
{
    int n = blockIdx.x, tid = threadIdx.x;
    float ws = wsum_buf[n];
    int e0 = eidx[2*n], e1 = eidx[2*n+1];
    float z0[8], z1[8];
#pragma unroll
    for (int r = 0; r < 8; r++){ z0[r] = z2s[n*16+r]; z1[r] = z2s[n*16+8+r]; }
    const float* crow = C2 + (size_t)n * D_DIM;
    float* po = out + (size_t)n * D_DIM;
    for (int d = tid; d < D_DIM; d += 256){
        float c = crow[d] + ws * b2[d];
        const float4* q0 = (const float4*)&B2[((size_t)e0*D_DIM + d)*R_RANK];
        const float4* q1 = (const float4*)&B2[((size_t)e1*D_DIM + d)*R_RANK];
        float4 u0 = q0[0], u1 = q0[1], v0 = q1[0], v1 = q1[1];
        c += z0[0]*u0.x + z0[1]*u0.y + z0[2]*u0.z + z0[3]*u0.w
           + z0[4]*u1.x + z0[5]*u1.y + z0[6]*u1.z + z0[7]*u1.w;
        c += z1[0]*v0.x + z1[1]*v0.y + z1[2]*v0.z + z1[3]*v0.w
           + z1[4]*v1.x + z1[5]*v1.y + z1[6]*v1.z + z1[7]*v1.w;
        po[d] = c;
    }
}

// ============================================================================
// z2 — verbatim R1
// ============================================================================
__global__ __launch_bounds__(256) void z2_kernel(const float* __restrict__ A2)
{
    int n = blockIdx.x;
    int k = blockIdx.y;
    int tid = threadIdx.x;
    int e = eidx[2 * n + k];
    const float* h = h_buf + (size_t)k * N_TOK * F_DIM + (size_t)n * F_DIM;
    const float* a2 = A2 + (size_t)e * R_RANK * F_DIM;

    float acc[R_RANK];
#pragma unroll
    for (int r = 0; r < R_RANK; r++) acc[r] = 0.f;
    for (int f = tid * 4; f < F_DIM; f += 1024) {
        float4 hv = *(const float4*)(h + f);
#pragma unroll
        for (int r = 0; r < R_RANK; r++) {
            float4 av = *(const float4*)(a2 + (size_t)r * F_DIM + f);
            acc[r] += hv.x * av.x + hv.y * av.y + hv.z * av.z + hv.w * av.w;
        }
    }
    __shared__ float red[R_RANK][8];
#pragma unroll
    for (int r = 0; r < R_RANK; r++) {
        float v = acc[r];
        for (int o = 16; o > 0; o >>= 1) v += __shfl_down_sync(0xffffffffu, v, o);
        if ((tid & 31) == 0) red[r][tid >> 5] = v;
    }
    __syncthreads();
    if (tid < R_RANK) {
        float v = 0.f;
#pragma unroll
        for (int w = 0; w < 8; w++) v += red[tid][w];
        z2s[n * 16 + k * 8 + tid] = v * SCALING * ew[2 * n + k];
    }
}

// ============================================================================
// Verifiers (sampled fp32 ground truth) + gated SIMT fallbacks
// ============================================================================
__global__ __launch_bounds__(256) void ver_fc1(
    const float* __restrict__ x, const float* __restrict__ W1,
    const float* __restrict__ b1, const float* __restrict__ B1)
{
    int s = blockIdx.x, tid = threadIdx.x;
    int n = (s * 97) & (N_TOK - 1);
    int f = (s * 53 + 7) & (F_DIM - 1);
    float p = 0.f;
    for (int d = tid; d < D_DIM; d += 256)
        p += x[(size_t)n*D_DIM + d] * W1[(size_t)f*D_DIM + d];
    for (int o = 16; o > 0; o >>= 1) p += __shfl_down_sync(0xffffffffu, p, o);
    __shared__ float red[8];
    if ((tid & 31) == 0) red[tid >> 5] = p;
    __syncthreads();
    if (tid == 0){
        float c = b1[f];
#pragma unroll
        for (int w = 0; w < 8; w++) c += red[w];
        int e0 = eidx[2*n], e1 = eidx[2*n+1];
        float l0 = 0.f, l1 = 0.f;
#pragma unroll
        for (int r = 0; r < 8; r++){
            l0 += z1c[n*16+r]   * B1[((size_t)e0*F_DIM+f)*R_RANK + r];
            l1 += z1c[n*16+8+r] * B1[((size_t)e1*F_DIM+f)*R_RANK + r];
        }
        float h0 = gelu_new(c + l0), h1 = gelu_new(c + l1);
        float hg0 = h_buf[(size_t)n*F_DIM + f];
        float hg1 = h_buf[(size_t)N_TOK*F_DIM + (size_t)n*F_DIM + f];
        if (fabsf(hg0 - h0) > 3e-3f*fmaxf(1.f, fabsf(h0)) ||
            fabsf(hg1 - h1) > 3e-3f*fmaxf(1.f, fabsf(h1)))
            atomicAdd(&gf1, 1);
    }
}

__global__ __launch_bounds__(256) void ver_fc2(
    const float* __restrict__ W2, const float* __restrict__ b2,
    const float* __restrict__ B2, const float* __restrict__ out)
{
    int s = blockIdx.x, tid = threadIdx.x;
    int n = (s * 89 + 3) & (N_TOK - 1);
    int d = (s * 41 + 5) & (D_DIM - 1);
    float p = 0.f;
    for (int f = tid; f < F_DIM; f += 256)
        p += (g_hi[(size_t)n*F_DIM + f] + g_lo[(size_t)n*F_DIM + f])
           * W2[(size_t)d*F_DIM + f];
    for (int o = 16; o > 0; o >>= 1) p += __shfl_down_sync(0xffffffffu, p, o);
    __shared__ float red[8];
    if ((tid & 31) == 0) red[tid >> 5] = p;
    __syncthreads();
    if (tid == 0){
        float c = wsum_buf[n] * b2[d];
#pragma unroll
        for (int w = 0; w < 8; w++) c += red[w];
        int e0 = eidx[2*n], e1 = eidx[2*n+1];
#pragma unroll
        for (int r = 0; r < 8; r++){
            c += z2s[n*16+r]   * B2[((size_t)e0*D_DIM+d)*R_RANK + r];
            c += z2s[n*16+8+r] * B2[((size_t)e1*D_DIM+d)*R_RANK + r];
        }
        float o_ = out[(size_t)n*D_DIM + d];
        if (fabsf(o_ - c) > 3e-3f*fmaxf(1.f, fabsf(c)))
            atomicAdd(&gf2, 1);
    }
}

// fallback fc1 (gated): exact SIMT recompute of h planes + g split
__global__ __launch_bounds__(256, 2) void fc1_fb(
    const float* __restrict__ A, const float* __restrict__ B,
    const float* __restrict__ b1, const float* __restrict__ B1)
{
    if (gf1 == 0) return;
    const int K = D_DIM;
    int bn = blockIdx.x, bm = blockIdx.y;
    int tid = threadIdx.x;
    __shared__ float As[BK][BM + 4];
    __shared__ float Bs[BK][BN + 4];
    float acc[TM][TN];
#pragma unroll
    for (int i = 0; i < TM; i++)
#pragma unroll
        for (int j = 0; j < TN; j++) acc[i][j] = 0.f;
    int tx = tid % 16, ty = tid / 16;
    const float* Ab = A + (size_t)bm * BM * K;
    const float* Bb = B + (size_t)bn * BN * K;
    int rowL = tid >> 2;
    int colL = (tid & 3) * 4;
    for (int k0 = 0; k0 < K; k0 += BK) {
#pragma unroll
        for (int i = 0; i < 2; i++) {
            float4 a = *(const float4*)(Ab + (size_t)(rowL + i * 64) * K + k0 + colL);
            As[colL + 0][rowL + i * 64] = a.x;
            As[colL + 1][rowL + i * 64] = a.y;
            As[colL + 2][rowL + i * 64] = a.z;
            As[colL + 3][rowL + i * 64] = a.w;
            float4 b = *(const float4*)(Bb + (size_t)(rowL + i * 64) * K + k0 + colL);
            Bs[colL + 0][rowL + i * 64] = b.x;
            Bs[colL + 1][rowL + i * 64] = b.y;
            Bs[colL + 2][rowL + i * 64] = b.z;
            Bs[colL + 3][rowL + i * 64] = b.w;
        }
        __syncthreads();
#pragma unroll
        for (int kk = 0; kk < BK; kk++) {
            float4 a0 = *(const float4*)&As[kk][ty * TM];
            float4 a1 = *(const float4*)&As[kk][ty * TM + 4];
            float4 b0 = *(const float4*)&Bs[kk][tx * TN];
            float4 b1v = *(const float4*)&Bs[kk][tx * TN + 4];
            float ra[8] = {a0.x, a0.y, a0.z, a0.w, a1.x, a1.y, a1.z, a1.w};
            float rb[8] = {b0.x, b0.y, b0.z, b0.w, b1v.x, b1v.y, b1v.z, b1v.w};
#pragma unroll
            for (int i = 0; i < TM; i++)
#pragma unroll
                for (int j = 0; j < TN; j++) acc[i][j] += ra[i] * rb[j];
        }
        __syncthreads();
    }
    int nrow0 = bm * BM + ty * TM;
    int fcol0 = bn * BN + tx * TN;
#pragma unroll
    for (int i = 0; i < TM; i++) {
        int n = nrow0 + i;
        int e0 = eidx[2 * n], e1 = eidx[2 * n + 1];
        float w0 = ew[2 * n], w1 = ew[2 * n + 1];
        const float4* zp = (const float4*)&z1c[n * 16];
        float4 z0a = zp[0], z0b = zp[1], z1a = zp[2], z1b = zp[3];
#pragma unroll
        for (int j = 0; j < TN; j++) {
            int f = fcol0 + j;
            float c = acc[i][j] + b1[f];
            const float4* q0 = (const float4*)&B1[((size_t)e0 * F_DIM + f) * R_RANK];
            float4 u0 = q0[0], u1 = q0[1];
            float l0 = z0a.x * u0.x + z0a.y * u0.y + z0a.z * u0.z + z0a.w * u0.w
                     + z0b.x * u1.x + z0b.y * u1.y + z0b.z * u1.z + z0b.w * u1.w;
            const float4* q1 = (const float4*)&B1[((size_t)e1 * F_DIM + f) * R_RANK];
            float4 v0 = q1[0], v1 = q1[1];
            float l1 = z1a.x * v0.x + z1a.y * v0.y + z1a.z * v0.z + z1a.w * v0.w
                     + z1b.x * v1.x + z1b.y * v1.y + z1b.z * v1.z + z1b.w * v1.w;
            float h0 = gelu_new(c + l0);
            float h1 = gelu_new(c + l1);
            float g = w0 * h0 + w1 * h1;
            size_t off = (size_t)n * F_DIM + f;
            h_buf[off] = h0;
            h_buf[off + (size_t)N_TOK * F_DIM] = h1;
            float gh = wmma::__float_to_tf32(g);
            g_hi[off] = gh;
            g_lo[off] = wmma::__float_to_tf32(g - gh);
        }
    }
}

// fallback fc2 (gated): exact SIMT from (g_hi+g_lo)
__global__ __launch_bounds__(256, 2) void fc2_fb(
    const float* __restrict__ B, const float* __restrict__ b2,
    const float* __restrict__ B2, float* __restrict__ out)
{
    if (gf2 == 0 && gf1 == 0) return;
    const int K = F_DIM;
    int bn = blockIdx.x, bm = blockIdx.y;
    int tid = threadIdx.x;
    __shared__ float As[BK][BM + 4];
    __shared__ float Bs[BK][BN + 4];
    float acc[TM][TN];
#pragma unroll
    for (int i = 0; i < TM; i++)
#pragma unroll
        for (int j = 0; j < TN; j++) acc[i][j] = 0.f;
    int tx = tid % 16, ty = tid / 16;
    const float* Ah = g_hi + (size_t)bm * BM * K;
    const float* Al = g_lo + (size_t)bm * BM * K;
    const float* Bb = B + (size_t)bn * BN * K;
    int rowL = tid >> 2;
    int colL = (tid & 3) * 4;
    for (int k0 = 0; k0 < K; k0 += BK) {
#pragma unroll
        for (int i = 0; i < 2; i++) {
            size_t ao = (size_t)(rowL + i * 64) * K + k0 + colL;
            float4 ah = *(const float4*)(Ah + ao);
            float4 al = *(const float4*)(Al + ao);
            As[colL + 0][rowL + i * 64] = ah.x + al.x;
            As[colL + 1][rowL + i * 64] = ah.y + al.y;
            As[colL + 2][rowL + i * 64] = ah.z + al.z;
            As[colL + 3][rowL + i * 64] = ah.w + al.w;
            float4 b = *(const float4*)(Bb + ao);
            Bs[colL + 0][rowL + i * 64] = b.x;
            Bs[colL + 1][rowL + i * 64] = b.y;
            Bs[colL + 2][rowL + i * 64] = b.z;
            Bs[colL + 3][rowL + i * 64] = b.w;
        }
        __syncthreads();
#pragma unroll
        for (int kk = 0; kk < BK; kk++) {
            float4 a0 = *(const float4*)&As[kk][ty * TM];
            float4 a1 = *(const float4*)&As[kk][ty * TM + 4];
            float4 b0 = *(const float4*)&Bs[kk][tx * TN];
            float4 b1v = *(const float4*)&Bs[kk][tx * TN + 4];
            float ra[8] = {a0.x, a0.y, a0.z, a0.w, a1.x, a1.y, a1.z, a1.w};
            float rb[8] = {b0.x, b0.y, b0.z, b0.w, b1v.x, b1v.y, b1v.z, b1v.w};
#pragma unroll
            for (int i = 0; i < TM; i++)
#pragma unroll
                for (int j = 0; j < TN; j++) acc[i][j] += ra[i] * rb[j];
        }
        __syncthreads();
    }
    int nrow0 = bm * BM + ty * TM;
    int dcol0 = bn * BN + tx * TN;
#pragma unroll
    for (int i = 0; i < TM; i++) {
        int n = nrow0 + i;
        float ws = wsum_buf[n];
        int e0 = eidx[2 * n], e1 = eidx[2 * n + 1];
        const float4* zp = (const float4*)&z2s[n * 16];
        float4 z0a = zp[0], z0b = zp[1], z1a = zp[2], z1b = zp[3];
#pragma unroll
        for (int j = 0; j < TN; j++) {
            int d = dcol0 + j;
            float c = acc[i][j] + ws * b2[d];
            const float4* q0 = (const float4*)&B2[((size_t)e0 * D_DIM + d) * R_RANK];
            float4 u0 = q0[0], u1 = q0[1];
            c += z0a.x * u0.x + z0a.y * u0.y + z0a.z * u0.z + z0a.w * u0.w
               + z0b.x * u1.x + z0b.y * u1.y + z0b.z * u1.z + z0b.w * u1.w;
            const float4* q1 = (const float4*)&B2[((size_t)e1 * D_DIM + d) * R_RANK];
            float4 v0 = q1[0], v1 = q1[1];
            c += z1a.x * v0.x + z1a.y * v0.y + z1a.z * v0.z + z1a.w * v0.w
               + z1b.x * v1.x + z1b.y * v1.y + z1b.z * v1.z + z1b.w * v1.w;
            out[(size_t)n * D_DIM + d] = c;
        }
    }
}

// ------------------------- launch ------------------------------------------
extern "C" void kernel_launch(void* const* d_in, const int* in_sizes, int n_in,
                              void* d_out, int out_size)
{
    (void)in_sizes; (void)n_in; (void)out_size;
    const float* x  = (const float*)d_in[0];
    const float* Wr = (const float*)d_in[1];
    const float* br = (const float*)d_in[2];
    const float* W1 = (const float*)d_in[3];
    const float* b1 = (const float*)d_in[4];
    const float* W2 = (const float*)d_in[5];
    const float* b2 = (const float*)d_in[6];
    const float* A1 = (const float*)d_in[7];
    const float* B1 = (const float*)d_in[8];
    const float* A2 = (const float*)d_in[9];
    const float* B2 = (const float*)d_in[10];
    float* out = (float*)d_out;

    reset_kernel<<<1, 1>>>();
    router_kernel<<<N_TOK, 256>>>(x, Wr, br, A1);
    cvt_split<<<N_TOK, 256>>>(x,  x_hi, x_lo, D_DIM);
    cvt_split<<<F_DIM, 256>>>(W1, w1h, w1l, D_DIM);
    cvt_split<<<D_DIM, 256>>>(W2, w2h, w2l, F_DIM);

    // fc1 = x @ W1^T via 3 tf32 passes
    dim3 g1(F_DIM/128, N_TOK/128);
    gemm_pass<<<g1, 256>>>(x_hi, w1h, C1, D_DIM, F_DIM, 1);
    gemm_pass<<<g1, 256>>>(x_hi, w1l, C1, D_DIM, F_DIM, 0);
    gemm_pass<<<g1, 256>>>(x_lo, w1h, C1, D_DIM, F_DIM, 0);
    fc1_epi<<<N_TOK, 256>>>(b1, B1);
    ver_fc1<<<1024, 256>>>(x, W1, b1, B1);
    fc1_fb<<<dim3(F_DIM/BN, N_TOK/BM), 256>>>(x, W1, b1, B1);

    z2_kernel<<<dim3(N_TOK, 2), 256>>>(A2);

    // fc2 = g @ W2^T via 3 tf32 passes
    dim3 g2(D_DIM/128, N_TOK/128);
    gemm_pass<<<g2, 256>>>(g_hi, w2h, C2, F_DIM, D_DIM, 1);
    gemm_pass<<<g2, 256>>>(g_hi, w2l, C2, F_DIM, D_DIM, 0);
    gemm_pass<<<g2, 256>>>(g_lo, w2h, C2, F_DIM, D_DIM, 0);
    fc2_epi<<<N_TOK, 256>>>(b2, B2, out);
    ver_fc2<<<512, 256>>>(W2, b2, B2, out);
    fc2_fb<<<dim3(D_DIM/BN, N_TOK/BM), 256>>>(W2, b2, B2, out);
}

// round 11
// speedup vs baseline: 17.2533x; 17.2533x over previous
#include <cuda_runtime.h>
#include <mma.h>
#include <math.h>
#include <stdint.h>

using namespace nvcuda;

#define N_TOK 4096
#define D_DIM 2048
#define F_DIM 8192
#define E_EXP 8
#define R_RANK 8
#define SCALING 2.0f

#define BM 128
#define BN 128
#define BK 16
#define TM 8
#define TN 8

// ---------------- scratch (kept ~384MB, same as working R9) -----------------
__device__ float g_buf[(size_t)N_TOK * F_DIM];
__device__ float h_buf[2ull * N_TOK * F_DIM];
__device__ float z1c[N_TOK * 16];
__device__ float z2s[N_TOK * 16];
__device__ int   eidx[N_TOK * 2];
__device__ float ew[N_TOK * 2];
__device__ float wsum_buf[N_TOK];
__device__ int gf1, gf2;

__device__ __forceinline__ float gelu_new(float x) {
    float x3 = x * x * x;
    float t = tanhf(0.7978845608028654f * (x + 0.044715f * x3));
    return 0.5f * x * (1.0f + t);
}

__global__ void reset_kernel(){ gf1 = 0; gf2 = 0; }

// ---------------- router — verbatim R1 ---------------------------------------
__global__ __launch_bounds__(256) void router_kernel(
    const float* __restrict__ x, const float* __restrict__ Wr,
    const float* __restrict__ br, const float* __restrict__ A1)
{
    int n = blockIdx.x;
    int tid = threadIdx.x;
    __shared__ float xs[D_DIM];
    __shared__ float red[16][8];
    __shared__ int s_idx[2];

    for (int d = tid; d < D_DIM; d += 256) xs[d] = x[(size_t)n * D_DIM + d];
    __syncthreads();

    float acc[E_EXP];
#pragma unroll
    for (int e = 0; e < E_EXP; e++) acc[e] = 0.f;
    for (int d = tid; d < D_DIM; d += 256) {
        float xv = xs[d];
#pragma unroll
        for (int e = 0; e < E_EXP; e++) acc[e] += xv * Wr[e * D_DIM + d];
    }
#pragma unroll
    for (int e = 0; e < E_EXP; e++) {
        float v = acc[e];
        for (int o = 16; o > 0; o >>= 1) v += __shfl_down_sync(0xffffffffu, v, o);
        if ((tid & 31) == 0) red[e][tid >> 5] = v;
    }
    __syncthreads();

    if (tid == 0) {
        float lg[E_EXP];
#pragma unroll
        for (int e = 0; e < E_EXP; e++) {
            float v = 0.f;
#pragma unroll
            for (int w = 0; w < 8; w++) v += red[e][w];
            lg[e] = v + br[e];
        }
        float mx = lg[0];
#pragma unroll
        for (int e = 1; e < E_EXP; e++) mx = fmaxf(mx, lg[e]);
        float p[E_EXP], se = 0.f;
#pragma unroll
        for (int e = 0; e < E_EXP; e++) { p[e] = expf(lg[e] - mx); se += p[e]; }
        float inv = 1.0f / se;
#pragma unroll
        for (int e = 0; e < E_EXP; e++) p[e] *= inv;
        int i0 = 0;
#pragma unroll
        for (int e = 1; e < E_EXP; e++) if (p[e] > p[i0]) i0 = e;
        int i1 = -1;
#pragma unroll
        for (int e = 0; e < E_EXP; e++) {
            if (e == i0) continue;
            if (i1 < 0 || p[e] > p[i1]) i1 = e;
        }
        s_idx[0] = i0; s_idx[1] = i1;
        eidx[2 * n] = i0; eidx[2 * n + 1] = i1;
        ew[2 * n] = p[i0]; ew[2 * n + 1] = p[i1];
        wsum_buf[n] = p[i0] + p[i1];
    }
    __syncthreads();

    int e0 = s_idx[0], e1 = s_idx[1];
    float u[16];
#pragma unroll
    for (int i = 0; i < 16; i++) u[i] = 0.f;
    for (int d = tid; d < D_DIM; d += 256) {
        float xv = xs[d];
#pragma unroll
        for (int r = 0; r < R_RANK; r++) {
            u[r]     += xv * A1[((size_t)e0 * R_RANK + r) * D_DIM + d];
            u[8 + r] += xv * A1[((size_t)e1 * R_RANK + r) * D_DIM + d];
        }
    }
    __syncthreads();
#pragma unroll
    for (int i = 0; i < 16; i++) {
        float v = u[i];
        for (int o = 16; o > 0; o >>= 1) v += __shfl_down_sync(0xffffffffu, v, o);
        if ((tid & 31) == 0) red[i][tid >> 5] = v;
    }
    __syncthreads();
    if (tid < 16) {
        float v = 0.f;
#pragma unroll
        for (int w = 0; w < 8; w++) v += red[tid][w];
        z1c[n * 16 + tid] = v * SCALING;
    }
}

// ============================================================================
// Fused tf32 x3 GEMM — conversions hoisted to the smem loader.
// smem stage (single-buffered, 40KB): Ah[2560] Al[2560] Bh[2560] Bl[2560]
// ============================================================================
typedef wmma::fragment<wmma::matrix_a, 16,16,8, wmma::precision::tf32, wmma::row_major> TFA;
typedef wmma::fragment<wmma::matrix_b, 16,16,8, wmma::precision::tf32, wmma::col_major> TFB;
typedef wmma::fragment<wmma::accumulator, 16,16,8, float> TFC;

__device__ __forceinline__ void ldg_tile(float4* r, const float* g, size_t stride, int tid){
#pragma unroll
    for (int i = 0; i < 2; i++){
        int idx = tid + i * 256;
        int row = idx >> 2, c = (idx & 3) * 4;
        r[i] = *(const float4*)(g + (size_t)row * stride + c);
    }
}
// convert once + store hi/lo tiles (hi at base, lo at base+2560)
__device__ __forceinline__ void cvt_sts(float* base, const float4* r, int tid){
#pragma unroll
    for (int i = 0; i < 2; i++){
        int idx = tid + i * 256;
        int row = idx >> 2, c = (idx & 3) * 4;
        float4 v = r[i];
        float4 h, l;
        h.x = wmma::__float_to_tf32(v.x); l.x = wmma::__float_to_tf32(v.x - h.x);
        h.y = wmma::__float_to_tf32(v.y); l.y = wmma::__float_to_tf32(v.y - h.y);
        h.z = wmma::__float_to_tf32(v.z); l.z = wmma::__float_to_tf32(v.z - h.z);
        h.w = wmma::__float_to_tf32(v.w); l.w = wmma::__float_to_tf32(v.w - h.w);
        *(float4*)(base + row * 20 + c)        = h;
        *(float4*)(base + 2560 + row * 20 + c) = l;
    }
}

__device__ __forceinline__ void gemm_tf32(
    TFC (&acc)[2][4],
    const float* Ag, const float* Bg, int K, float* sm)
{
    const int tid = threadIdx.x, wid = tid >> 5;
    const int wr = wid & 3, wc = wid >> 2;
#pragma unroll
    for (int i = 0; i < 2; i++)
#pragma unroll
    for (int j = 0; j < 4; j++) wmma::fill_fragment(acc[i][j], 0.f);

    float4 ra[2], rb[2];
    ldg_tile(ra, Ag, K, tid);
    ldg_tile(rb, Bg, K, tid);
    cvt_sts(sm,        ra, tid);
    cvt_sts(sm + 5120, rb, tid);
    __syncthreads();

    const int nch = K / BK;
    for (int c = 0; c < nch; c++){
        if (c + 1 < nch){
            ldg_tile(ra, Ag + (size_t)(c+1)*BK, K, tid);
            ldg_tile(rb, Bg + (size_t)(c+1)*BK, K, tid);
        }
        const float* Ah = sm;
        const float* Al = sm + 2560;
        const float* Bh = sm + 5120;
        const float* Bl = sm + 7680;
#pragma unroll
        for (int k8 = 0; k8 < 2; k8++){
            TFA ah[2], al[2];
#pragma unroll
            for (int i = 0; i < 2; i++){
                wmma::load_matrix_sync(ah[i], Ah + (wr*32 + i*16)*20 + k8*8, 20);
                wmma::load_matrix_sync(al[i], Al + (wr*32 + i*16)*20 + k8*8, 20);
            }
#pragma unroll
            for (int j = 0; j < 4; j++){
                TFB bh, bl;
                wmma::load_matrix_sync(bh, Bh + (wc*64 + j*16)*20 + k8*8, 20);
                wmma::load_matrix_sync(bl, Bl + (wc*64 + j*16)*20 + k8*8, 20);
#pragma unroll
                for (int i = 0; i < 2; i++){
                    wmma::mma_sync(acc[i][j], ah[i], bh, acc[i][j]);
                    wmma::mma_sync(acc[i][j], ah[i], bl, acc[i][j]);
                    wmma::mma_sync(acc[i][j], al[i], bh, acc[i][j]);
                }
            }
        }
        __syncthreads();
        if (c + 1 < nch){
            cvt_sts(sm,        ra, tid);
            cvt_sts(sm + 5120, rb, tid);
        }
        __syncthreads();
    }
}

// ============================================================================
// fc1: x @ W1^T -> epilogue (+b1, LoRA1, gelu) -> h0,h1,g
// ============================================================================
__global__ __launch_bounds__(256) void fc1_tf32(
    const float* __restrict__ x, const float* __restrict__ W1,
    const float* __restrict__ b1, const float* __restrict__ B1)
{
    __shared__ __align__(16) float sm[10240];
    int bn = blockIdx.x, bm = blockIdx.y;
    int tid = threadIdx.x, wid = tid >> 5, wr = wid & 3, wc = wid >> 2;
    TFC acc[2][4];

    gemm_tf32(acc, x + (size_t)bm*128*D_DIM, W1 + (size_t)bn*128*D_DIM, D_DIM, sm);

    float* Cs = sm;   // 64 x 136 = 8704 floats
    for (int r = 0; r < 2; r++){
        __syncthreads();
        if ((wr >> 1) == r){
            int rl = (wr & 1) * 32;
#pragma unroll
            for (int i = 0; i < 2; i++)
#pragma unroll
            for (int j = 0; j < 4; j++)
                wmma::store_matrix_sync(Cs + (size_t)(rl+i*16)*136 + wc*64 + j*16,
                                        acc[i][j], 136, wmma::mem_row_major);
        }
        __syncthreads();

        int row_l = tid >> 2;
        int n = bm*128 + r*64 + row_l;
        int c0 = (tid & 3) * 32;
        int e0 = eidx[2*n], e1 = eidx[2*n+1];
        float w0 = ew[2*n], w1w = ew[2*n+1];
        float z0[8], z1[8];
#pragma unroll
        for (int q = 0; q < 8; q++){ z0[q] = z1c[n*16+q]; z1[q] = z1c[n*16+8+q]; }
        const float* crow = &Cs[(size_t)row_l*136];
        for (int jj = 0; jj < 32; jj += 2){
            int col = c0 + jj;
            int f = bn*128 + col;
            float ca = crow[col]   + b1[f];
            float cb = crow[col+1] + b1[f+1];
            const float4* q0 = (const float4*)&B1[((size_t)e0*F_DIM + f)*R_RANK];
            const float4* q1 = (const float4*)&B1[((size_t)e1*F_DIM + f)*R_RANK];
            float l0a=0.f, l0b=0.f, l1a=0.f, l1b=0.f;
#pragma unroll
            for (int q = 0; q < 2; q++){
                float4 u0=q0[q], u2=q0[2+q], v0=q1[q], v2=q1[2+q];
                l0a += z0[q*4+0]*u0.x + z0[q*4+1]*u0.y + z0[q*4+2]*u0.z + z0[q*4+3]*u0.w;
                l0b += z0[q*4+0]*u2.x + z0[q*4+1]*u2.y + z0[q*4+2]*u2.z + z0[q*4+3]*u2.w;
                l1a += z1[q*4+0]*v0.x + z1[q*4+1]*v0.y + z1[q*4+2]*v0.z + z1[q*4+3]*v0.w;
                l1b += z1[q*4+0]*v2.x + z1[q*4+1]*v2.y + z1[q*4+2]*v2.z + z1[q*4+3]*v2.w;
            }
            float h0a = gelu_new(ca + l0a), h0b_ = gelu_new(cb + l0b);
            float h1a = gelu_new(ca + l1a), h1b_ = gelu_new(cb + l1b);
            size_t off = (size_t)n*F_DIM + f;
            *(float2*)&h_buf[off] = make_float2(h0a, h0b_);
            *(float2*)&h_buf[off + (size_t)N_TOK*F_DIM] = make_float2(h1a, h1b_);
            *(float2*)&g_buf[off] = make_float2(w0*h0a + w1w*h1a, w0*h0b_ + w1w*h1b_);
        }
    }
}

// ============================================================================
// fc2: g @ W2^T -> epilogue (+ws*b2, LoRA2) -> out
// ============================================================================
__global__ __launch_bounds__(256) void fc2_tf32(
    const float* __restrict__ W2, const float* __restrict__ b2,
    const float* __restrict__ B2, float* __restrict__ out)
{
    __shared__ __align__(16) float sm[10240];
    int bn = blockIdx.x, bm = blockIdx.y;
    int tid = threadIdx.x, wid = tid >> 5, wr = wid & 3, wc = wid >> 2;
    TFC acc[2][4];

    gemm_tf32(acc, g_buf + (size_t)bm*128*F_DIM, W2 + (size_t)bn*128*F_DIM, F_DIM, sm);

    float* Cs = sm;
    for (int r = 0; r < 2; r++){
        __syncthreads();
        if ((wr >> 1) == r){
            int rl = (wr & 1) * 32;
#pragma unroll
            for (int i = 0; i < 2; i++)
#pragma unroll
            for (int j = 0; j < 4; j++)
                wmma::store_matrix_sync(Cs + (size_t)(rl+i*16)*136 + wc*64 + j*16,
                                        acc[i][j], 136, wmma::mem_row_major);
        }
        __syncthreads();

        int row_l = tid >> 2;
        int n = bm*128 + r*64 + row_l;
        int c0 = (tid & 3) * 32;
        float ws = wsum_buf[n];
        int e0 = eidx[2*n], e1 = eidx[2*n+1];
        float z0[8], z1[8];
#pragma unroll
        for (int q = 0; q < 8; q++){ z0[q] = z2s[n*16+q]; z1[q] = z2s[n*16+8+q]; }
        const float* crow = &Cs[(size_t)row_l*136];
        for (int jj = 0; jj < 32; jj++){
            int col = c0 + jj;
            int d = bn*128 + col;
            float c = crow[col] + ws*b2[d];
            const float4* q0 = (const float4*)&B2[((size_t)e0*D_DIM + d)*R_RANK];
            const float4* q1 = (const float4*)&B2[((size_t)e1*D_DIM + d)*R_RANK];
            float4 u0=q0[0], u1=q0[1], v0=q1[0], v1=q1[1];
            c += z0[0]*u0.x + z0[1]*u0.y + z0[2]*u0.z + z0[3]*u0.w
               + z0[4]*u1.x + z0[5]*u1.y + z0[6]*u1.z + z0[7]*u1.w;
            c += z1[0]*v0.x + z1[1]*v0.y + z1[2]*v0.z + z1[3]*v0.w
               + z1[4]*v1.x + z1[5]*v1.y + z1[6]*v1.z + z1[7]*v1.w;
            out[(size_t)n*D_DIM + d] = c;
        }
    }
}

// ============================================================================
// z2 — verbatim R1
// ============================================================================
__global__ __launch_bounds__(256) void z2_kernel(const float* __restrict__ A2)
{
    int n = blockIdx.x;
    int k = blockIdx.y;
    int tid = threadIdx.x;
    int e = eidx[2 * n + k];
    const float* h = h_buf + (size_t)k * N_TOK * F_DIM + (size_t)n * F_DIM;
    const float* a2 = A2 + (size_t)e * R_RANK * F_DIM;

    float acc[R_RANK];
#pragma unroll
    for (int r = 0; r < R_RANK; r++) acc[r] = 0.f;
    for (int f = tid * 4; f < F_DIM; f += 1024) {
        float4 hv = *(const float4*)(h + f);
#pragma unroll
        for (int r = 0; r < R_RANK; r++) {
            float4 av = *(const float4*)(a2 + (size_t)r * F_DIM + f);
            acc[r] += hv.x * av.x + hv.y * av.y + hv.z * av.z + hv.w * av.w;
        }
    }
    __shared__ float red[R_RANK][8];
#pragma unroll
    for (int r = 0; r < R_RANK; r++) {
        float v = acc[r];
        for (int o = 16; o > 0; o >>= 1) v += __shfl_down_sync(0xffffffffu, v, o);
        if ((tid & 31) == 0) red[r][tid >> 5] = v;
    }
    __syncthreads();
    if (tid < R_RANK) {
        float v = 0.f;
#pragma unroll
        for (int w = 0; w < 8; w++) v += red[tid][w];
        z2s[n * 16 + k * 8 + tid] = v * SCALING * ew[2 * n + k];
    }
}

// ============================================================================
// Verifiers (sampled fp32 ground truth) + gated SIMT fallbacks (R1 kernels)
// ============================================================================
__global__ __launch_bounds__(256) void ver_fc1(
    const float* __restrict__ x, const float* __restrict__ W1,
    const float* __restrict__ b1, const float* __restrict__ B1)
{
    int s = blockIdx.x, tid = threadIdx.x;
    int n = (s * 97) & (N_TOK - 1);
    int f = (s * 53 + 7) & (F_DIM - 1);
    float p = 0.f;
    for (int d = tid; d < D_DIM; d += 256)
        p += x[(size_t)n*D_DIM + d] * W1[(size_t)f*D_DIM + d];
    for (int o = 16; o > 0; o >>= 1) p += __shfl_down_sync(0xffffffffu, p, o);
    __shared__ float red[8];
    if ((tid & 31) == 0) red[tid >> 5] = p;
    __syncthreads();
    if (tid == 0){
        float c = b1[f];
#pragma unroll
        for (int w = 0; w < 8; w++) c += red[w];
        int e0 = eidx[2*n], e1 = eidx[2*n+1];
        float l0 = 0.f, l1 = 0.f;
#pragma unroll
        for (int r = 0; r < 8; r++){
            l0 += z1c[n*16+r]   * B1[((size_t)e0*F_DIM+f)*R_RANK + r];
            l1 += z1c[n*16+8+r] * B1[((size_t)e1*F_DIM+f)*R_RANK + r];
        }
        float h0 = gelu_new(c + l0), h1 = gelu_new(c + l1);
        float hg0 = h_buf[(size_t)n*F_DIM + f];
        float hg1 = h_buf[(size_t)N_TOK*F_DIM + (size_t)n*F_DIM + f];
        if (fabsf(hg0 - h0) > 3e-3f*fmaxf(1.f, fabsf(h0)) ||
            fabsf(hg1 - h1) > 3e-3f*fmaxf(1.f, fabsf(h1)))
            atomicAdd(&gf1, 1);
    }
}

__global__ __launch_bounds__(256) void ver_fc2(
    const float* __restrict__ W2, const float* __restrict__ b2,
    const float* __restrict__ B2, const float* __restrict__ out)
{
    int s = blockIdx.x, tid = threadIdx.x;
    int n = (s * 89 + 3) & (N_TOK - 1);
    int d = (s * 41 + 5) & (D_DIM - 1);
    float p = 0.f;
    for (int f = tid; f < F_DIM; f += 256)
        p += g_buf[(size_t)n*F_DIM + f] * W2[(size_t)d*F_DIM + f];
    for (int o = 16; o > 0; o >>= 1) p += __shfl_down_sync(0xffffffffu, p, o);
    __shared__ float red[8];
    if ((tid & 31) == 0) red[tid >> 5] = p;
    __syncthreads();
    if (tid == 0){
        float c = wsum_buf[n] * b2[d];
#pragma unroll
        for (int w = 0; w < 8; w++) c += red[w];
        int e0 = eidx[2*n], e1 = eidx[2*n+1];
#pragma unroll
        for (int r = 0; r < 8; r++){
            c += z2s[n*16+r]   * B2[((size_t)e0*D_DIM+d)*R_RANK + r];
            c += z2s[n*16+8+r] * B2[((size_t)e1*D_DIM+d)*R_RANK + r];
        }
        float o_ = out[(size_t)n*D_DIM + d];
        if (fabsf(o_ - c) > 3e-3f*fmaxf(1.f, fabsf(c)))
            atomicAdd(&gf2, 1);
    }
}

__global__ __launch_bounds__(256, 2) void fc1_fb(
    const float* __restrict__ A, const float* __restrict__ B,
    const float* __restrict__ b1, const float* __restrict__ B1)
{
    if (gf1 == 0) return;
    const int K = D_DIM;
    int bn = blockIdx.x, bm = blockIdx.y;
    int tid = threadIdx.x;
    __shared__ float As[BK][BM + 4];
    __shared__ float Bs[BK][BN + 4];
    float acc[TM][TN];
#pragma unroll
    for (int i = 0; i < TM; i++)
#pragma unroll
        for (int j = 0; j < TN; j++) acc[i][j] = 0.f;
    int tx = tid % 16, ty = tid / 16;
    const float* Ab = A + (size_t)bm * BM * K;
    const float* Bb = B + (size_t)bn * BN * K;
    int rowL = tid >> 2;
    int colL = (tid & 3) * 4;
    for (int k0 = 0; k0 < K; k0 += BK) {
#pragma unroll
        for (int i = 0; i < 2; i++) {
            float4 a = *(const float4*)(Ab + (size_t)(rowL + i * 64) * K + k0 + colL);
            As[colL + 0][rowL + i * 64] = a.x;
            As[colL + 1][rowL + i * 64] = a.y;
            As[colL + 2][rowL + i * 64] = a.z;
            As[colL + 3][rowL + i * 64] = a.w;
            float4 b = *(const float4*)(Bb + (size_t)(rowL + i * 64) * K + k0 + colL);
            Bs[colL + 0][rowL + i * 64] = b.x;
            Bs[colL + 1][rowL + i * 64] = b.y;
            Bs[colL + 2][rowL + i * 64] = b.z;
            Bs[colL + 3][rowL + i * 64] = b.w;
        }
        __syncthreads();
#pragma unroll
        for (int kk = 0; kk < BK; kk++) {
            float4 a0 = *(const float4*)&As[kk][ty * TM];
            float4 a1 = *(const float4*)&As[kk][ty * TM + 4];
            float4 b0 = *(const float4*)&Bs[kk][tx * TN];
            float4 b1v = *(const float4*)&Bs[kk][tx * TN + 4];
            float ra[8] = {a0.x, a0.y, a0.z, a0.w, a1.x, a1.y, a1.z, a1.w};
            float rb[8] = {b0.x, b0.y, b0.z, b0.w, b1v.x, b1v.y, b1v.z, b1v.w};
#pragma unroll
            for (int i = 0; i < TM; i++)
#pragma unroll
                for (int j = 0; j < TN; j++) acc[i][j] += ra[i] * rb[j];
        }
        __syncthreads();
    }
    int nrow0 = bm * BM + ty * TM;
    int fcol0 = bn * BN + tx * TN;
#pragma unroll
    for (int i = 0; i < TM; i++) {
        int n = nrow0 + i;
        int e0 = eidx[2 * n], e1 = eidx[2 * n + 1];
        float w0 = ew[2 * n], w1 = ew[2 * n + 1];
        const float4* zp = (const float4*)&z1c[n * 16];
        float4 z0a = zp[0], z0b = zp[1], z1a = zp[2], z1b = zp[3];
#pragma unroll
        for (int j = 0; j < TN; j++) {
            int f = fcol0 + j;
            float c = acc[i][j] + b1[f];
            const float4* q0 = (const float4*)&B1[((size_t)e0 * F_DIM + f) * R_RANK];
            float4 u0 = q0[0], u1 = q0[1];
            float l0 = z0a.x * u0.x + z0a.y * u0.y + z0a.z * u0.z + z0a.w * u0.w
                     + z0b.x * u1.x + z0b.y * u1.y + z0b.z * u1.z + z0b.w * u1.w;
            const float4* q1 = (const float4*)&B1[((size_t)e1 * F_DIM + f) * R_RANK];
            float4 v0 = q1[0], v1 = q1[1];
            float l1 = z1a.x * v0.x + z1a.y * v0.y + z1a.z * v0.z + z1a.w * v0.w
                     + z1b.x * v1.x + z1b.y * v1.y + z1b.z * v1.z + z1b.w * v1.w;
            float h0 = gelu_new(c + l0);
            float h1 = gelu_new(c + l1);
            size_t off = (size_t)n * F_DIM + f;
            h_buf[off] = h0;
            h_buf[off + (size_t)N_TOK * F_DIM] = h1;
            g_buf[off] = w0 * h0 + w1 * h1;
        }
    }
}

__global__ __launch_bounds__(256, 2) void fc2_fb(
    const float* __restrict__ B, const float* __restrict__ b2,
    const float* __restrict__ B2, float* __restrict__ out)
{
    if (gf2 == 0 && gf1 == 0) return;
    const int K = F_DIM;
    int bn = blockIdx.x, bm = blockIdx.y;
    int tid = threadIdx.x;
    __shared__ float As[BK][BM + 4];
    __shared__ float Bs[BK][BN + 4];
    float acc[TM][TN];
#pragma unroll
    for (int i = 0; i < TM; i++)
#pragma unroll
        for (int j = 0; j < TN; j++) acc[i][j] = 0.f;
    int tx = tid % 16, ty = tid / 16;
    const float* Ab = g_buf + (size_t)bm * BM * K;
    const float* Bb = B + (size_t)bn * BN * K;
    int rowL = tid >> 2;
    int colL = (tid & 3) * 4;
    for (int k0 = 0; k0 < K; k0 += BK) {
#pragma unroll
        for (int i = 0; i < 2; i++) {
            float4 a = *(const float4*)(Ab + (size_t)(rowL + i * 64) * K + k0 + colL);
            As[colL + 0][rowL + i * 64] = a.x;
            As[colL + 1][rowL + i * 64] = a.y;
            As[colL + 2][rowL + i * 64] = a.z;
            As[colL + 3][rowL + i * 64] = a.w;
            float4 b = *(const float4*)(Bb + (size_t)(rowL + i * 64) * K + k0 + colL);
            Bs[colL + 0][rowL + i * 64] = b.x;
            Bs[colL + 1][rowL + i * 64] = b.y;
            Bs[colL + 2][rowL + i * 64] = b.z;
            Bs[colL + 3][rowL + i * 64] = b.w;
        }
        __syncthreads();
#pragma unroll
        for (int kk = 0; kk < BK; kk++) {
            float4 a0 = *(const float4*)&As[kk][ty * TM];
            float4 a1 = *(const float4*)&As[kk][ty * TM + 4];
            float4 b0 = *(const float4*)&Bs[kk][tx * TN];
            float4 b1v = *(const float4*)&Bs[kk][tx * TN + 4];
            float ra[8] = {a0.x, a0.y, a0.z, a0.w, a1.x, a1.y, a1.z, a1.w};
            float rb[8] = {b0.x, b0.y, b0.z, b0.w, b1v.x, b1v.y, b1v.z, b1v.w};
#pragma unroll
            for (int i = 0; i < TM; i++)
#pragma unroll
                for (int j = 0; j < TN; j++) acc[i][j] += ra[i] * rb[j];
        }
        __syncthreads();
    }
    int nrow0 = bm * BM + ty * TM;
    int dcol0 = bn * BN + tx * TN;
#pragma unroll
    for (int i = 0; i < TM; i++) {
        int n = nrow0 + i;
        float ws = wsum_buf[n];
        int e0 = eidx[2 * n], e1 = eidx[2 * n + 1];
        const float4* zp = (const float4*)&z2s[n * 16];
        float4 z0a = zp[0], z0b = zp[1], z1a = zp[2], z1b = zp[3];
#pragma unroll
        for (int j = 0; j < TN; j++) {
            int d = dcol0 + j;
            float c = acc[i][j] + ws * b2[d];
            const float4* q0 = (const float4*)&B2[((size_t)e0 * D_DIM + d) * R_RANK];
            float4 u0 = q0[0], u1 = q0[1];
            c += z0a.x * u0.x + z0a.y * u0.y + z0a.z * u0.z + z0a.w * u0.w
               + z0b.x * u1.x + z0b.y * u1.y + z0b.z * u1.z + z0b.w * u1.w;
            const float4* q1 = (const float4*)&B2[((size_t)e1 * D_DIM + d) * R_RANK];
            float4 v0 = q1[0], v1 = q1[1];
            c += z1a.x * v0.x + z1a.y * v0.y + z1a.z * v0.z + z1a.w * v0.w
               + z1b.x * v1.x + z1b.y * v1.y + z1b.z * v1.z + z1b.w * v1.w;
            out[(size_t)n * D_DIM + d] = c;
        }
    }
}

// ------------------------- launch ------------------------------------------
extern "C" void kernel_launch(void* const* d_in, const int* in_sizes, int n_in,
                              void* d_out, int out_size)
{
    (void)in_sizes; (void)n_in; (void)out_size;
    const float* x  = (const float*)d_in[0];
    const float* Wr = (const float*)d_in[1];
    const float* br = (const float*)d_in[2];
    const float* W1 = (const float*)d_in[3];
    const float* b1 = (const float*)d_in[4];
    const float* W2 = (const float*)d_in[5];
    const float* b2 = (const float*)d_in[6];
    const float* A1 = (const float*)d_in[7];
    const float* B1 = (const float*)d_in[8];
    const float* A2 = (const float*)d_in[9];
    const float* B2 = (const float*)d_in[10];
    float* out = (float*)d_out;

    reset_kernel<<<1, 1>>>();
    router_kernel<<<N_TOK, 256>>>(x, Wr, br, A1);

    fc1_tf32<<<dim3(F_DIM/128, N_TOK/128), 256>>>(x, W1, b1, B1);
    ver_fc1<<<1024, 256>>>(x, W1, b1, B1);
    fc1_fb<<<dim3(F_DIM/BN, N_TOK/BM), 256>>>(x, W1, b1, B1);

    z2_kernel<<<dim3(N_TOK, 2), 256>>>(A2);

    fc2_tf32<<<dim3(D_DIM/128, N_TOK/128), 256>>>(W2, b2, B2, out);
    ver_fc2<<<512, 256>>>(W2, b2, B2, out);
    fc2_fb<<<dim3(D_DIM/BN, N_TOK/BM), 256>>>(W2, b2, B2, out);
}

// round 12
// speedup vs baseline: 29.4175x; 1.7050x over previous
#include <cuda_runtime.h>
#include <math.h>
#include <stdint.h>

#define N_TOK 4096
#define D_DIM 2048
#define F_DIM 8192
#define E_EXP 8
#define R_RANK 8
#define SCALING 2.0f

#define BM 128
#define BN 128
#define BK 16
#define TM 8
#define TN 8

typedef unsigned long long ull;

// ---------------- packed f32x2 helpers (Blackwell sm_100+) -------------------
__device__ __forceinline__ ull pk2f(float a, float b){
    ull r;
    asm("mov.b64 %0, {%1, %2};"
        : "=l"(r) : "r"(__float_as_uint(a)), "r"(__float_as_uint(b)));
    return r;
}
__device__ __forceinline__ void fma2(ull& d, ull a, ull b){
    asm("fma.rn.f32x2 %0, %1, %2, %0;" : "+l"(d) : "l"(a), "l"(b));
}
__device__ __forceinline__ float2 unpk(ull v){
    unsigned lo, hi;
    asm("mov.b64 {%0, %1}, %2;" : "=r"(lo), "=r"(hi) : "l"(v));
    return make_float2(__uint_as_float(lo), __uint_as_float(hi));
}

// ---------------- scratch ----------------------------------------------------
__device__ float g_buf[(size_t)N_TOK * F_DIM];
__device__ float h_buf[2ull * N_TOK * F_DIM];
__device__ float z1c[N_TOK * 16];
__device__ float z2s[N_TOK * 16];
__device__ int   eidx[N_TOK * 2];
__device__ float ew[N_TOK * 2];
__device__ float wsum_buf[N_TOK];

__device__ __forceinline__ float gelu_new(float x) {
    float x3 = x * x * x;
    float t = tanhf(0.7978845608028654f * (x + 0.044715f * x3));
    return 0.5f * x * (1.0f + t);
}

// ---------------- router — verbatim R1 ---------------------------------------
__global__ __launch_bounds__(256) void router_kernel(
    const float* __restrict__ x, const float* __restrict__ Wr,
    const float* __restrict__ br, const float* __restrict__ A1)
{
    int n = blockIdx.x;
    int tid = threadIdx.x;
    __shared__ float xs[D_DIM];
    __shared__ float red[16][8];
    __shared__ int s_idx[2];

    for (int d = tid; d < D_DIM; d += 256) xs[d] = x[(size_t)n * D_DIM + d];
    __syncthreads();

    float acc[E_EXP];
#pragma unroll
    for (int e = 0; e < E_EXP; e++) acc[e] = 0.f;
    for (int d = tid; d < D_DIM; d += 256) {
        float xv = xs[d];
#pragma unroll
        for (int e = 0; e < E_EXP; e++) acc[e] += xv * Wr[e * D_DIM + d];
    }
#pragma unroll
    for (int e = 0; e < E_EXP; e++) {
        float v = acc[e];
        for (int o = 16; o > 0; o >>= 1) v += __shfl_down_sync(0xffffffffu, v, o);
        if ((tid & 31) == 0) red[e][tid >> 5] = v;
    }
    __syncthreads();

    if (tid == 0) {
        float lg[E_EXP];
#pragma unroll
        for (int e = 0; e < E_EXP; e++) {
            float v = 0.f;
#pragma unroll
            for (int w = 0; w < 8; w++) v += red[e][w];
            lg[e] = v + br[e];
        }
        float mx = lg[0];
#pragma unroll
        for (int e = 1; e < E_EXP; e++) mx = fmaxf(mx, lg[e]);
        float p[E_EXP], se = 0.f;
#pragma unroll
        for (int e = 0; e < E_EXP; e++) { p[e] = expf(lg[e] - mx); se += p[e]; }
        float inv = 1.0f / se;
#pragma unroll
        for (int e = 0; e < E_EXP; e++) p[e] *= inv;
        int i0 = 0;
#pragma unroll
        for (int e = 1; e < E_EXP; e++) if (p[e] > p[i0]) i0 = e;
        int i1 = -1;
#pragma unroll
        for (int e = 0; e < E_EXP; e++) {
            if (e == i0) continue;
            if (i1 < 0 || p[e] > p[i1]) i1 = e;
        }
        s_idx[0] = i0; s_idx[1] = i1;
        eidx[2 * n] = i0; eidx[2 * n + 1] = i1;
        ew[2 * n] = p[i0]; ew[2 * n + 1] = p[i1];
        wsum_buf[n] = p[i0] + p[i1];
    }
    __syncthreads();

    int e0 = s_idx[0], e1 = s_idx[1];
    float u[16];
#pragma unroll
    for (int i = 0; i < 16; i++) u[i] = 0.f;
    for (int d = tid; d < D_DIM; d += 256) {
        float xv = xs[d];
#pragma unroll
        for (int r = 0; r < R_RANK; r++) {
            u[r]     += xv * A1[((size_t)e0 * R_RANK + r) * D_DIM + d];
            u[8 + r] += xv * A1[((size_t)e1 * R_RANK + r) * D_DIM + d];
        }
    }
    __syncthreads();
#pragma unroll
    for (int i = 0; i < 16; i++) {
        float v = u[i];
        for (int o = 16; o > 0; o >>= 1) v += __shfl_down_sync(0xffffffffu, v, o);
        if ((tid & 31) == 0) red[i][tid >> 5] = v;
    }
    __syncthreads();
    if (tid < 16) {
        float v = 0.f;
#pragma unroll
        for (int w = 0; w < 8; w++) v += red[tid][w];
        z1c[n * 16 + tid] = v * SCALING;
    }
}

// ---------------------------------------------------------------------------
// fc1: base = x @ W1^T with packed f32x2 FMA; epilogue per-expert LoRA + gelu.
// ---------------------------------------------------------------------------
__global__ __launch_bounds__(256, 2) void fc1_kernel(
    const float* __restrict__ A,   // x [N, D]
    const float* __restrict__ B,   // W1 [F, D]
    const float* __restrict__ b1,
    const float* __restrict__ B1)  // [E, F, R]
{
    const int K = D_DIM;
    int bn = blockIdx.x, bm = blockIdx.y;
    int tid = threadIdx.x;
    __shared__ __align__(16) float As[BK][BM + 4];
    __shared__ __align__(16) float Bs[BK][BN + 4];
    ull acc2[TM][TN / 2];
#pragma unroll
    for (int i = 0; i < TM; i++)
#pragma unroll
        for (int j = 0; j < TN / 2; j++) acc2[i][j] = 0ull;

    int tx = tid % 16, ty = tid / 16;
    const float* Ab = A + (size_t)bm * BM * K;
    const float* Bb = B + (size_t)bn * BN * K;
    int rowL = tid >> 2;
    int colL = (tid & 3) * 4;

    for (int k0 = 0; k0 < K; k0 += BK) {
#pragma unroll
        for (int i = 0; i < 2; i++) {
            float4 a = *(const float4*)(Ab + (size_t)(rowL + i * 64) * K + k0 + colL);
            As[colL + 0][rowL + i * 64] = a.x;
            As[colL + 1][rowL + i * 64] = a.y;
            As[colL + 2][rowL + i * 64] = a.z;
            As[colL + 3][rowL + i * 64] = a.w;
            float4 b = *(const float4*)(Bb + (size_t)(rowL + i * 64) * K + k0 + colL);
            Bs[colL + 0][rowL + i * 64] = b.x;
            Bs[colL + 1][rowL + i * 64] = b.y;
            Bs[colL + 2][rowL + i * 64] = b.z;
            Bs[colL + 3][rowL + i * 64] = b.w;
        }
        __syncthreads();
#pragma unroll
        for (int kk = 0; kk < BK; kk++) {
            float4 a0 = *(const float4*)&As[kk][ty * TM];
            float4 a1 = *(const float4*)&As[kk][ty * TM + 4];
            const ull* bp = (const ull*)&Bs[kk][tx * TN];
            ull rb0 = bp[0], rb1 = bp[1], rb2 = bp[2], rb3 = bp[3];
            float ra[8] = {a0.x, a0.y, a0.z, a0.w, a1.x, a1.y, a1.z, a1.w};
#pragma unroll
            for (int i = 0; i < TM; i++) {
                ull ra2 = pk2f(ra[i], ra[i]);
                fma2(acc2[i][0], ra2, rb0);
                fma2(acc2[i][1], ra2, rb1);
                fma2(acc2[i][2], ra2, rb2);
                fma2(acc2[i][3], ra2, rb3);
            }
        }
        __syncthreads();
    }

    float acc[TM][TN];
#pragma unroll
    for (int i = 0; i < TM; i++)
#pragma unroll
        for (int j = 0; j < TN / 2; j++) {
            float2 v = unpk(acc2[i][j]);
            acc[i][2 * j] = v.x;
            acc[i][2 * j + 1] = v.y;
        }

    int nrow0 = bm * BM + ty * TM;
    int fcol0 = bn * BN + tx * TN;
#pragma unroll
    for (int i = 0; i < TM; i++) {
        int n = nrow0 + i;
        int e0 = eidx[2 * n], e1 = eidx[2 * n + 1];
        float w0 = ew[2 * n], w1 = ew[2 * n + 1];
        const float4* zp = (const float4*)&z1c[n * 16];
        float4 z0a = zp[0], z0b = zp[1], z1a = zp[2], z1b = zp[3];
        float h0v[TN], h1v[TN], gv[TN];
#pragma unroll
        for (int j = 0; j < TN; j++) {
            int f = fcol0 + j;
            float c = acc[i][j] + b1[f];
            const float4* q0 = (const float4*)&B1[((size_t)e0 * F_DIM + f) * R_RANK];
            float4 u0 = q0[0], u1 = q0[1];
            float l0 = z0a.x * u0.x + z0a.y * u0.y + z0a.z * u0.z + z0a.w * u0.w
                     + z0b.x * u1.x + z0b.y * u1.y + z0b.z * u1.z + z0b.w * u1.w;
            const float4* q1 = (const float4*)&B1[((size_t)e1 * F_DIM + f) * R_RANK];
            float4 v0 = q1[0], v1 = q1[1];
            float l1 = z1a.x * v0.x + z1a.y * v0.y + z1a.z * v0.z + z1a.w * v0.w
                     + z1b.x * v1.x + z1b.y * v1.y + z1b.z * v1.z + z1b.w * v1.w;
            float h0 = gelu_new(c + l0);
            float h1 = gelu_new(c + l1);
            h0v[j] = h0; h1v[j] = h1;
            gv[j] = w0 * h0 + w1 * h1;
        }
        size_t off = (size_t)n * F_DIM + fcol0;
        *(float4*)&h_buf[off]     = make_float4(h0v[0], h0v[1], h0v[2], h0v[3]);
        *(float4*)&h_buf[off + 4] = make_float4(h0v[4], h0v[5], h0v[6], h0v[7]);
        size_t off1 = off + (size_t)N_TOK * F_DIM;
        *(float4*)&h_buf[off1]     = make_float4(h1v[0], h1v[1], h1v[2], h1v[3]);
        *(float4*)&h_buf[off1 + 4] = make_float4(h1v[4], h1v[5], h1v[6], h1v[7]);
        *(float4*)&g_buf[off]     = make_float4(gv[0], gv[1], gv[2], gv[3]);
        *(float4*)&g_buf[off + 4] = make_float4(gv[4], gv[5], gv[6], gv[7]);
    }
}

// ---------------------------------------------------------------------------
// z2 — verbatim R1
// ---------------------------------------------------------------------------
__global__ __launch_bounds__(256) void z2_kernel(const float* __restrict__ A2)
{
    int n = blockIdx.x;
    int k = blockIdx.y;
    int tid = threadIdx.x;
    int e = eidx[2 * n + k];
    const float* h = h_buf + (size_t)k * N_TOK * F_DIM + (size_t)n * F_DIM;
    const float* a2 = A2 + (size_t)e * R_RANK * F_DIM;

    float acc[R_RANK];
#pragma unroll
    for (int r = 0; r < R_RANK; r++) acc[r] = 0.f;

    for (int f = tid * 4; f < F_DIM; f += 1024) {
        float4 hv = *(const float4*)(h + f);
#pragma unroll
        for (int r = 0; r < R_RANK; r++) {
            float4 av = *(const float4*)(a2 + (size_t)r * F_DIM + f);
            acc[r] += hv.x * av.x + hv.y * av.y + hv.z * av.z + hv.w * av.w;
        }
    }

    __shared__ float red[R_RANK][8];
#pragma unroll
    for (int r = 0; r < R_RANK; r++) {
        float v = acc[r];
        for (int o = 16; o > 0; o >>= 1) v += __shfl_down_sync(0xffffffffu, v, o);
        if ((tid & 31) == 0) red[r][tid >> 5] = v;
    }
    __syncthreads();
    if (tid < R_RANK) {
        float v = 0.f;
#pragma unroll
        for (int w = 0; w < 8; w++) v += red[tid][w];
        z2s[n * 16 + k * 8 + tid] = v * SCALING * ew[2 * n + k];
    }
}

// ---------------------------------------------------------------------------
// fc2: out = g @ W2^T with packed f32x2 FMA; epilogue bias + z2 LoRA.
// ---------------------------------------------------------------------------
__global__ __launch_bounds__(256, 2) void fc2_kernel(
    const float* __restrict__ B,   // W2 [D, F]
    const float* __restrict__ b2,
    const float* __restrict__ B2,  // [E, D, R]
    float* __restrict__ out)
{
    const int K = F_DIM;
    int bn = blockIdx.x, bm = blockIdx.y;
    int tid = threadIdx.x;
    __shared__ __align__(16) float As[BK][BM + 4];
    __shared__ __align__(16) float Bs[BK][BN + 4];
    ull acc2[TM][TN / 2];
#pragma unroll
    for (int i = 0; i < TM; i++)
#pragma unroll
        for (int j = 0; j < TN / 2; j++) acc2[i][j] = 0ull;

    int tx = tid % 16, ty = tid / 16;
    const float* Ab = g_buf + (size_t)bm * BM * K;
    const float* Bb = B + (size_t)bn * BN * K;
    int rowL = tid >> 2;
    int colL = (tid & 3) * 4;

    for (int k0 = 0; k0 < K; k0 += BK) {
#pragma unroll
        for (int i = 0; i < 2; i++) {
            float4 a = *(const float4*)(Ab + (size_t)(rowL + i * 64) * K + k0 + colL);
            As[colL + 0][rowL + i * 64] = a.x;
            As[colL + 1][rowL + i * 64] = a.y;
            As[colL + 2][rowL + i * 64] = a.z;
            As[colL + 3][rowL + i * 64] = a.w;
            float4 b = *(const float4*)(Bb + (size_t)(rowL + i * 64) * K + k0 + colL);
            Bs[colL + 0][rowL + i * 64] = b.x;
            Bs[colL + 1][rowL + i * 64] = b.y;
            Bs[colL + 2][rowL + i * 64] = b.z;
            Bs[colL + 3][rowL + i * 64] = b.w;
        }
        __syncthreads();
#pragma unroll
        for (int kk = 0; kk < BK; kk++) {
            float4 a0 = *(const float4*)&As[kk][ty * TM];
            float4 a1 = *(const float4*)&As[kk][ty * TM + 4];
            const ull* bp = (const ull*)&Bs[kk][tx * TN];
            ull rb0 = bp[0], rb1 = bp[1], rb2 = bp[2], rb3 = bp[3];
            float ra[8] = {a0.x, a0.y, a0.z, a0.w, a1.x, a1.y, a1.z, a1.w};
#pragma unroll
            for (int i = 0; i < TM; i++) {
                ull ra2 = pk2f(ra[i], ra[i]);
                fma2(acc2[i][0], ra2, rb0);
                fma2(acc2[i][1], ra2, rb1);
                fma2(acc2[i][2], ra2, rb2);
                fma2(acc2[i][3], ra2, rb3);
            }
        }
        __syncthreads();
    }

    float acc[TM][TN];
#pragma unroll
    for (int i = 0; i < TM; i++)
#pragma unroll
        for (int j = 0; j < TN / 2; j++) {
            float2 v = unpk(acc2[i][j]);
            acc[i][2 * j] = v.x;
            acc[i][2 * j + 1] = v.y;
        }

    int nrow0 = bm * BM + ty * TM;
    int dcol0 = bn * BN + tx * TN;
#pragma unroll
    for (int i = 0; i < TM; i++) {
        int n = nrow0 + i;
        float ws = wsum_buf[n];
        int e0 = eidx[2 * n], e1 = eidx[2 * n + 1];
        const float4* zp = (const float4*)&z2s[n * 16];
        float4 z0a = zp[0], z0b = zp[1], z1a = zp[2], z1b = zp[3];
        float ov[TN];
#pragma unroll
        for (int j = 0; j < TN; j++) {
            int d = dcol0 + j;
            float c = acc[i][j] + ws * b2[d];
            const float4* q0 = (const float4*)&B2[((size_t)e0 * D_DIM + d) * R_RANK];
            float4 u0 = q0[0], u1 = q0[1];
            c += z0a.x * u0.x + z0a.y * u0.y + z0a.z * u0.z + z0a.w * u0.w
               + z0b.x * u1.x + z0b.y * u1.y + z0b.z * u1.z + z0b.w * u1.w;
            const float4* q1 = (const float4*)&B2[((size_t)e1 * D_DIM + d) * R_RANK];
            float4 v0 = q1[0], v1 = q1[1];
            c += z1a.x * v0.x + z1a.y * v0.y + z1a.z * v0.z + z1a.w * v0.w
               + z1b.x * v1.x + z1b.y * v1.y + z1b.z * v1.z + z1b.w * v1.w;
            ov[j] = c;
        }
        size_t off = (size_t)n * D_DIM + dcol0;
        *(float4*)&out[off]     = make_float4(ov[0], ov[1], ov[2], ov[3]);
        *(float4*)&out[off + 4] = make_float4(ov[4], ov[5], ov[6], ov[7]);
    }
}

extern "C" void kernel_launch(void* const* d_in, const int* in_sizes, int n_in,
                              void* d_out, int out_size)
{
    (void)in_sizes; (void)n_in; (void)out_size;
    const float* x  = (const float*)d_in[0];
    const float* Wr = (const float*)d_in[1];
    const float* br = (const float*)d_in[2];
    const float* W1 = (const float*)d_in[3];
    const float* b1 = (const float*)d_in[4];
    const float* W2 = (const float*)d_in[5];
    const float* b2 = (const float*)d_in[6];
    const float* A1 = (const float*)d_in[7];
    const float* B1 = (const float*)d_in[8];
    const float* A2 = (const float*)d_in[9];
    const float* B2 = (const float*)d_in[10];
    float* out = (float*)d_out;

    router_kernel<<<N_TOK, 256>>>(x, Wr, br, A1);
    fc1_kernel<<<dim3(F_DIM / BN, N_TOK / BM), 256>>>(x, W1, b1, B1);
    z2_kernel<<<dim3(N_TOK, 2), 256>>>(A2);
    fc2_kernel<<<dim3(D_DIM / BN, N_TOK / BM), 256>>>(W2, b2, B2, out);
}